// round 16
// baseline (speedup 1.0000x reference)
#include <cuda_runtime.h>
#include <cuda.h>
#include <cuda_fp16.h>
#include <cstdint>
#include <dlfcn.h>
#include <math.h>

// ---------------------------------------------------------------------------
// ConvLSTM B=64 H=W=32 CIN=64 HID=128 L=3 rep=3. Out [h_last|hs(3)|cs(3)].
// x-conv: direct fp16 implicit GEMM (precomputed Gx, fp32).
// h-conv: 1D-Winograd F(2,3) over y (4 points) x direct over x.
//   V[p] = y-transformed h; U[p] = y-transformed Wh. gates row-pair =
//   (m0+m1+m2, m1-m2-m3) + Gx, LSTM fused in epilogue.
// ---------------------------------------------------------------------------
#define BATCH   64
#define HH      32
#define WW      32
#define CIN_X   64
#define HID     128
#define GATES   512
#define MPOS    (BATCH*HH*WW)
#define PLANE   ((size_t)MPOS*HID)
#define GXPLANE ((size_t)MPOS*GATES)
#define KX      (9*CIN_X)              // 576
#define VPLANE  ((size_t)BATCH*16*32*HID)   // 4194304  (row-pair space)

// ---- x-conv (direct) tiling: 16 warps 8Mx2N, BM=256 ----
#define XN_TH       512
#define X_STAGES    4
#define X_ABYTES    32768
#define X_BBYTES    16384
#define X_STAGE     (X_ABYTES + X_BBYTES)
#define XSM_A(s)    ((s)*X_STAGE)
#define XSM_B(s)    (XSM_A(s) + X_ABYTES)
#define X_BAR       (X_STAGES*X_STAGE)
#define X_SMEM      (X_BAR + 128)

// ---- Winograd h-conv tiling: 8 warps m16 each, BM=128, N=32 ----
#define WG_NTH      256
#define WG_STAGES   4
#define WG_ABYTES   16384              // 128 rows x 128B
#define WG_BBYTES   4096               // 4 gates x 8 rows x 128B
#define WG_STAGE    (WG_ABYTES + WG_BBYTES)
#define WGSM_A(s)   ((s)*WG_STAGE)
#define WGSM_B(s)   (WGSM_A(s) + WG_ABYTES)
#define WG_BAR      (WG_STAGES*WG_STAGE)      // 81920
#define WG_SMEM     (WG_BAR + 128)
#define WG_NCHUNK   24                 // 4 points x 3 dx x 2 ch-halves

// ---------------------------------------------------------------------------
// Device scratch
// ---------------------------------------------------------------------------
__device__ __align__(1024) __half g_WxT[3 * GATES * KX];        // x-weights, perm
__device__ __align__(1024) __half g_UW [12 * GATES * 384];      // Winograd Wh [l*4+p][n][k]
__device__ __align__(1024) __half g_xP [(size_t)MPOS * CIN_X];  // x, perm fp16
__device__ __align__(1024) __half g_V  [12 * VPLANE];           // V planes [l*4+p]
__device__ __align__(1024) float  g_Gx [3 * GXPLANE];
__device__ __align__(1024) float  g_hbuf[2 * 3 * PLANE];        // natural fp32
__device__ __align__(1024) float  g_cbuf[2 * 3 * PLANE];

// ---------------------------------------------------------------------------
// PTX helpers
// ---------------------------------------------------------------------------
__device__ __forceinline__ uint32_t smem_u32(const void* p) {
    uint32_t a;
    asm("{ .reg .u64 t; cvta.to.shared.u64 t, %1; cvt.u32.u64 %0, t; }"
        : "=r"(a) : "l"(p));
    return a;
}
#define MBAR_INIT(addr, cnt) \
    asm volatile("mbarrier.init.shared.b64 [%0], %1;" :: "r"(addr), "r"(cnt) : "memory")
#define MBAR_ARRIVE(addr) \
    asm volatile("mbarrier.arrive.shared.b64 _, [%0];" :: "r"(addr) : "memory")
#define MBAR_EXPECT_TX(addr, bytes) \
    asm volatile("mbarrier.arrive.expect_tx.shared.b64 _, [%0], %1;" \
                 :: "r"(addr), "r"(bytes) : "memory")
#define MBAR_WAIT(addr, ph) do {                                              \
    uint32_t _m = (addr), _p = (ph), _d;                                      \
    asm volatile("{\n\t.reg .pred p;\n\t"                                     \
        "mbarrier.try_wait.parity.acquire.cta.shared::cta.b64 p, [%1], %2;\n\t" \
        "selp.b32 %0, 1, 0, p;\n\t}" : "=r"(_d) : "r"(_m), "r"(_p) : "memory");\
    if (!_d) {                                                                \
        asm volatile("{\n\t.reg .pred P1;\n\tWL_%=:\n\t"                      \
            "mbarrier.try_wait.parity.acquire.cta.shared::cta.b64 P1, [%0], %1, 0x989680;\n\t" \
            "@P1 bra.uni WD_%=;\n\tbra.uni WL_%=;\n\tWD_%=:\n\t}"             \
            :: "r"(_m), "r"(_p) : "memory");                                  \
    } } while (0)

#define TMA_LD_5D(dst, map, c0_, c1_, c2_, c3_, c4_, mbar) \
    asm volatile("cp.async.bulk.tensor.5d.shared::cta.global.tile.mbarrier::complete_tx::bytes " \
        "[%0], [%1, {%2, %3, %4, %5, %6}], [%7];" \
        :: "r"(dst), "l"(map), "r"(c0_), "r"(c1_), "r"(c2_), "r"(c3_), "r"(c4_), "r"(mbar) : "memory")
#define TMA_LD_3D(dst, map, c0_, c1_, c2_, mbar) \
    asm volatile("cp.async.bulk.tensor.3d.shared::cta.global.tile.mbarrier::complete_tx::bytes " \
        "[%0], [%1, {%2, %3, %4}], [%5];" \
        :: "r"(dst), "l"(map), "r"(c0_), "r"(c1_), "r"(c2_), "r"(mbar) : "memory")

__device__ __forceinline__ uint2 lds64(uint32_t addr) {
    uint2 r;
    asm("ld.shared.v2.b32 {%0,%1}, [%2];" : "=r"(r.x), "=r"(r.y) : "r"(addr));
    return r;
}
__device__ __forceinline__ void mma16(float* d, const uint32_t* a, const uint32_t* b) {
    asm volatile("mma.sync.aligned.m16n8k16.row.col.f32.f16.f16.f32 "
        "{%0,%1,%2,%3}, {%4,%5,%6,%7}, {%8,%9}, {%0,%1,%2,%3};"
        : "+f"(d[0]), "+f"(d[1]), "+f"(d[2]), "+f"(d[3])
        : "r"(a[0]), "r"(a[1]), "r"(a[2]), "r"(a[3]), "r"(b[0]), "r"(b[1]));
}
__device__ __forceinline__ int perm16(int k) {
    return 4 * ((k & 7) >> 1) + 2 * (k >> 3) + (k & 1);
}
__device__ __forceinline__ int bankperm64(int c, int row) {
    return ((((c >> 4) & 3) ^ (row & 3)) << 4) | perm16(c & 15);
}
__device__ __forceinline__ float sigm(float v) { return 1.f / (1.f + __expf(-v)); }

// ---------------------------------------------------------------------------
// x-conv: direct implicit GEMM (R15 config). Writes Gx = conv(x,Wx)+b, fp32.
// grid (256, 4, 3), 512 threads (16 warps = 8M x 2N).
// ---------------------------------------------------------------------------
__global__ __launch_bounds__(XN_TH, 1)
void conv_x(const __grid_constant__ CUtensorMap a_map,
            const __grid_constant__ CUtensorMap b_map,
            const float* __restrict__ bias)    // [3][512]
{
    extern __shared__ __align__(1024) char smem[];
    const uint32_t sb = smem_u32(smem);
    const int tid = threadIdx.x, lane = tid & 31, wid = tid >> 5;
    const int wm = wid & 7, wn = wid >> 3;
    const int l = blockIdx.z;

    const uint32_t FULL = sb + X_BAR, EMPTY = sb + X_BAR + 32;
    if (tid == 0) {
#pragma unroll
        for (int s = 0; s < X_STAGES; s++) {
            MBAR_INIT(FULL + 8*s, 1);
            MBAR_INIT(EMPTY + 8*s, 16);
        }
    }
    __syncthreads();

    const int c0 = blockIdx.y * 32;
    const int m0 = blockIdx.x * 256;
    const int bimg = m0 >> 10;
    const int y0 = (m0 >> 5) & 31;

    if (tid == 0) {
#pragma unroll
        for (int kc = 0; kc < X_STAGES; kc++) {
            MBAR_EXPECT_TX(FULL + 8*kc, (uint32_t)X_STAGE);
            const int dy = kc / 3 - 1, dx = kc % 3 - 1;
            TMA_LD_5D(sb + XSM_A(kc), &a_map, 0, dx, y0 + dy, bimg, 0, FULL + 8*kc);
#pragma unroll
            for (int g = 0; g < 4; g++)
                TMA_LD_3D(sb + XSM_B(kc) + g * 4096, &b_map, kc * 64, g * 128 + c0, l,
                          FULL + 8*kc);
        }
    }

    float acc[2][8][4];
#pragma unroll
    for (int mi = 0; mi < 2; mi++)
#pragma unroll
        for (int ni = 0; ni < 8; ni++)
#pragma unroll
            for (int j = 0; j < 4; j++) acc[mi][ni][j] = 0.f;

    const int q4 = lane >> 2, t4 = lane & 3;
    const uint32_t xorB = (uint32_t)(q4 & 3) << 5;

    for (int kc = 0; kc < 9; kc++) {
        const int s = kc & 3;
        const uint32_t u = (kc >> 2) & 1;
        MBAR_WAIT(FULL + 8*s, u);
        const int dxA = kc % 3 - 1;
        const uint32_t xorA = (uint32_t)((q4 + dxA) & 3) << 5;
        const uint32_t aW = sb + XSM_A(s) + (uint32_t)wm * 4096 + ((uint32_t)q4 << 7);
        const uint32_t bW = sb + XSM_B(s) + (uint32_t)wn * 2048 + ((uint32_t)q4 << 7);
#pragma unroll
        for (int ks = 0; ks < 4; ks++) {
            const uint32_t koffA = (((uint32_t)(ks * 32)) ^ xorA) + (uint32_t)(t4 * 8);
            const uint32_t koffB = (((uint32_t)(ks * 32)) ^ xorB) + (uint32_t)(t4 * 8);
            uint2 aLo[2], aHi[2];
#pragma unroll
            for (int mi = 0; mi < 2; mi++) {
                aLo[mi] = lds64(aW + (uint32_t)mi * 2048 + koffA);
                aHi[mi] = lds64(aW + (uint32_t)mi * 2048 + 1024 + koffA);
            }
            uint2 bfr[8];
#pragma unroll
            for (int g = 0; g < 4; g++)
#pragma unroll
                for (int s2 = 0; s2 < 2; s2++)
                    bfr[g*2+s2] = lds64(bW + (uint32_t)g * 4096 + (uint32_t)s2 * 1024 + koffB);
#pragma unroll
            for (int mi = 0; mi < 2; mi++) {
                const uint32_t af[4] = {aLo[mi].x, aHi[mi].x, aLo[mi].y, aHi[mi].y};
#pragma unroll
                for (int ni = 0; ni < 8; ni++)
                    mma16(acc[mi][ni], af, &bfr[ni].x);
            }
        }
        if (lane == 0) MBAR_ARRIVE(EMPTY + 8*s);
        if (tid == 0 && kc + X_STAGES < 9) {
            MBAR_WAIT(EMPTY + 8*s, u);
            MBAR_EXPECT_TX(FULL + 8*s, (uint32_t)X_STAGE);
            const int kn = kc + X_STAGES;
            const int dy = kn / 3 - 1, dx = kn % 3 - 1;
            TMA_LD_5D(sb + XSM_A(s), &a_map, 0, dx, y0 + dy, bimg, 0, FULL + 8*s);
#pragma unroll
            for (int g = 0; g < 4; g++)
                TMA_LD_3D(sb + XSM_B(s) + g * 4096, &b_map, kn * 64, g * 128 + c0, l,
                          FULL + 8*s);
        }
    }

    const float* bl = bias + (size_t)l * GATES;
    float* gxo = g_Gx + (size_t)l * GXPLANE;
#pragma unroll
    for (int mi = 0; mi < 2; mi++)
#pragma unroll
        for (int h = 0; h < 2; h++) {
            const int m = m0 + wm * 32 + mi * 16 + q4 + 8 * h;
            const int j = 2 * h;
#pragma unroll
            for (int g = 0; g < 4; g++)
#pragma unroll
                for (int s2 = 0; s2 < 2; s2++) {
                    const int gcol = g * 128 + c0 + (wn * 2 + s2) * 8 + t4 * 2;
                    const float2 bv = *(const float2*)(bl + gcol);
                    float2 v;
                    v.x = acc[mi][g*2+s2][j]   + bv.x;
                    v.y = acc[mi][g*2+s2][j+1] + bv.y;
                    *(float2*)(gxo + (size_t)m * GATES + gcol) = v;
                }
        }
}

// ---------------------------------------------------------------------------
// Winograd h-conv. grid (256, 16, 3): m-tile(128 rp-rows), c8-slice, layer.
// 8 warps, warp m16 x N32 (4 gates x 8ch). acc[4 points][4 gates][4].
// Epilogue: inverse y-transform + LSTM for the 2 spatial rows per rp.
// ---------------------------------------------------------------------------
__global__ __launch_bounds__(WG_NTH, 1)
void conv_wg(const __grid_constant__ CUtensorMap v_map,
             const __grid_constant__ CUtensorMap u_map,
             const char* __restrict__ c_in, size_t cin_stride,
             char* __restrict__ h_out,      size_t h_stride,
             char* __restrict__ c_out,      size_t cout_stride,
             float* __restrict__ h_dup)
{
    extern __shared__ __align__(1024) char smem[];
    const uint32_t sb = smem_u32(smem);
    const int tid = threadIdx.x, lane = tid & 31, wm = tid >> 5;
    const int l = blockIdx.z;
    const int c8 = blockIdx.y * 8;
    const int mt = blockIdx.x;
    const int m0 = mt * 128;
    const int b  = mt >> 2;
    const int rp0 = (mt & 3) * 4;

    const uint32_t FULL = sb + WG_BAR, EMPTY = sb + WG_BAR + 32;
    if (tid == 0) {
#pragma unroll
        for (int s = 0; s < WG_STAGES; s++) {
            MBAR_INIT(FULL + 8*s, 1);
            MBAR_INIT(EMPTY + 8*s, 8);
        }
    }
    __syncthreads();

    if (tid == 0) {
#pragma unroll
        for (int kc = 0; kc < WG_STAGES; kc++) {
            MBAR_EXPECT_TX(FULL + 8*kc, (uint32_t)WG_STAGE);
            const int p = kc / 6, r = kc % 6, dxi = r >> 1, half = r & 1;
            TMA_LD_5D(sb + WGSM_A(kc), &v_map, half * 64, dxi - 1, rp0, b,
                      l * 4 + p, FULL + 8*kc);
            const int k0 = dxi * 128 + half * 64;
#pragma unroll
            for (int g = 0; g < 4; g++)
                TMA_LD_3D(sb + WGSM_B(kc) + g * 1024, &u_map, k0, g * 128 + c8,
                          l * 4 + p, FULL + 8*kc);
        }
    }

    float acc[4][4][4];
#pragma unroll
    for (int p = 0; p < 4; p++)
#pragma unroll
        for (int g = 0; g < 4; g++)
#pragma unroll
            for (int j = 0; j < 4; j++) acc[p][g][j] = 0.f;

    const int q4 = lane >> 2, t4 = lane & 3;
    const uint32_t xorB = (uint32_t)(q4 & 3) << 5;

    for (int kc = 0; kc < WG_NCHUNK; kc++) {
        const int s = kc & 3;
        const uint32_t u = (kc >> 2) & 1;
        MBAR_WAIT(FULL + 8*s, u);
        const int p = kc / 6, r = kc % 6, dxi = r >> 1;
        const int dxA = dxi - 1;
        const uint32_t xorA = (uint32_t)((q4 + dxA) & 3) << 5;
        const uint32_t aW = sb + WGSM_A(s) + (uint32_t)wm * 2048 + ((uint32_t)q4 << 7);
        const uint32_t bW = sb + WGSM_B(s) + ((uint32_t)q4 << 7);
#pragma unroll
        for (int ks = 0; ks < 4; ks++) {
            const uint32_t koffA = (((uint32_t)(ks * 32)) ^ xorA) + (uint32_t)(t4 * 8);
            const uint32_t koffB = (((uint32_t)(ks * 32)) ^ xorB) + (uint32_t)(t4 * 8);
            const uint2 aLo = lds64(aW + koffA);
            const uint2 aHi = lds64(aW + 1024 + koffA);
            uint2 bfr[4];
#pragma unroll
            for (int g = 0; g < 4; g++)
                bfr[g] = lds64(bW + (uint32_t)g * 1024 + koffB);
            const uint32_t af[4] = {aLo.x, aHi.x, aLo.y, aHi.y};
#pragma unroll
            for (int g = 0; g < 4; g++)
                mma16(acc[p][g], af, &bfr[g].x);
        }
        if (lane == 0) MBAR_ARRIVE(EMPTY + 8*s);
        if (tid == 0 && kc + WG_STAGES < WG_NCHUNK) {
            MBAR_WAIT(EMPTY + 8*s, u);
            MBAR_EXPECT_TX(FULL + 8*s, (uint32_t)WG_STAGE);
            const int kn = kc + WG_STAGES;
            const int pn = kn / 6, rn = kn % 6, dxn = rn >> 1, hn = rn & 1;
            TMA_LD_5D(sb + WGSM_A(s), &v_map, hn * 64, dxn - 1, rp0, b,
                      l * 4 + pn, FULL + 8*s);
            const int k0 = dxn * 128 + hn * 64;
#pragma unroll
            for (int g = 0; g < 4; g++)
                TMA_LD_3D(sb + WGSM_B(s) + g * 1024, &u_map, k0, g * 128 + c8,
                          l * 4 + pn, FULL + 8*s);
        }
    }

    // ---- epilogue: inverse y-transform + LSTM ----
    const float* gxl = g_Gx + (size_t)l * GXPLANE;
    const float* cil = (const float*)(c_in + (size_t)l * cin_stride);
    float* hol = (float*)(h_out + (size_t)l * h_stride);
    float* col = (float*)(c_out + (size_t)l * cout_stride);
    float* hd  = (h_dup && l == 2) ? h_dup : nullptr;

#pragma unroll
    for (int h = 0; h < 2; h++) {
        const int mrp = m0 + wm * 16 + q4 + 8 * h;
        const int j = 2 * h;
        const int bb = mrp >> 9, rp = (mrp >> 5) & 15, x = mrp & 31;
        const int mo0 = (bb * 32 + 2 * rp) * 32 + x;   // spatial m for y0; y1 = +32
        const int ch = c8 + t4 * 2;
#pragma unroll
        for (int yy = 0; yy < 2; yy++) {
            const int mo = mo0 + yy * 32;
            float gate[4][2];
#pragma unroll
            for (int g = 0; g < 4; g++) {
                if (yy == 0) {
                    gate[g][0] = acc[0][g][j]   + acc[1][g][j]   + acc[2][g][j];
                    gate[g][1] = acc[0][g][j+1] + acc[1][g][j+1] + acc[2][g][j+1];
                } else {
                    gate[g][0] = acc[1][g][j]   - acc[2][g][j]   - acc[3][g][j];
                    gate[g][1] = acc[1][g][j+1] - acc[2][g][j+1] - acc[3][g][j+1];
                }
                const float2 gv = *(const float2*)(gxl + (size_t)mo * GATES + g * 128 + ch);
                gate[g][0] += gv.x;
                gate[g][1] += gv.y;
            }
            const float2 cv = *(const float2*)(cil + (size_t)mo * HID + ch);
            float2 cn, hnv;
            cn.x = sigm(gate[1][0]) * cv.x + sigm(gate[0][0]) * tanhf(gate[2][0]);
            cn.y = sigm(gate[1][1]) * cv.y + sigm(gate[0][1]) * tanhf(gate[2][1]);
            hnv.x = sigm(gate[3][0]) * tanhf(cn.x);
            hnv.y = sigm(gate[3][1]) * tanhf(cn.y);
            const size_t ob = (size_t)mo * HID + ch;
            *(float2*)(col + ob) = cn;
            *(float2*)(hol + ob) = hnv;
            if (hd) *(float2*)(hd + ob) = hnv;
        }
    }
}

// ---------------------------------------------------------------------------
// V transform: h (natural fp32) -> 4 y-transform point planes, fp16 + perm.
// idx over (l, b, rp, x, cpair).  v0=d0-d2 v1=d1+d2 v2=d2-d1 v3=d1-d3,
// d_i = h row 2rp-1+i (zero outside [0,32)).
// ---------------------------------------------------------------------------
__global__ void vtrans(const char* __restrict__ src, size_t src_stride)
{
    const int idx = blockIdx.x * blockDim.x + threadIdx.x;
    if (idx >= (3 << 21)) return;
    const int cp = idx & 63;
    const int x  = (idx >> 6) & 31;
    const int rp = (idx >> 11) & 15;
    const int b  = (idx >> 15) & 63;
    const int l  = idx >> 21;
    const int c  = cp * 2;

    const float* hp = (const float*)(src + (size_t)l * src_stride);
    float2 d[4];
#pragma unroll
    for (int i = 0; i < 4; i++) {
        const int y = 2 * rp - 1 + i;
        d[i] = (y >= 0 && y < 32)
             ? *(const float2*)(hp + ((size_t)(b * 32 + y) * 32 + x) * HID + c)
             : make_float2(0.f, 0.f);
    }
    float2 v[4];
    v[0] = make_float2(d[0].x - d[2].x, d[0].y - d[2].y);
    v[1] = make_float2(d[1].x + d[2].x, d[1].y + d[2].y);
    v[2] = make_float2(d[2].x - d[1].x, d[2].y - d[1].y);
    v[3] = make_float2(d[1].x - d[3].x, d[1].y - d[3].y);

    const int pos = (c & ~63) | bankperm64(c & 63, x);
    const size_t base = ((size_t)(b * 16 + rp) * 32 + x) * HID + pos;
#pragma unroll
    for (int p = 0; p < 4; p++)
        *(half2*)(g_V + (size_t)(l * 4 + p) * VPLANE + base) =
            __floats2half2_rn(v[p].x, v[p].y);
}

// ---------------------------------------------------------------------------
// Weight preps
// ---------------------------------------------------------------------------
__global__ void prep_w(const float* __restrict__ src, __half* __restrict__ dst,
                       int K, int total)
{
    int i = blockIdx.x * blockDim.x + threadIdx.x;
    if (i >= total) return;
    int n = i % GATES;
    int k = (i / GATES) % K;
    int l = i / (GATES * K);
    int kp = (k & ~63) | bankperm64(k & 63, n);
    dst[((size_t)l * GATES + n) * K + kp] = __float2half_rn(src[i]);
}

// Winograd y-transform of Wh: U[l*4+p][n][dx*128 + perm(cin)], fp16.
__global__ void prep_wg(const float* __restrict__ Wh)
{
    int i = blockIdx.x * blockDim.x + threadIdx.x;
    if (i >= 3 * 512 * 3 * 128) return;
    const int cin = i & 127;
    const int dxi = (i >> 7) % 3;
    const int n   = (i >> 7) / 3 % 512;
    const int l   = i / (128 * 3 * 512);

    float g0 = Wh[(((size_t)(l * 3 + 0) * 3 + dxi) * 128 + cin) * 512 + n];
    float g1 = Wh[(((size_t)(l * 3 + 1) * 3 + dxi) * 128 + cin) * 512 + n];
    float g2 = Wh[(((size_t)(l * 3 + 2) * 3 + dxi) * 128 + cin) * 512 + n];
    float u[4];
    u[0] = g0;
    u[1] = 0.5f * (g0 + g1 + g2);
    u[2] = 0.5f * (g0 - g1 + g2);
    u[3] = g2;
    const int kp = dxi * 128 + ((cin & ~63) | bankperm64(cin & 63, n));
#pragma unroll
    for (int p = 0; p < 4; p++)
        g_UW[((size_t)(l * 4 + p) * GATES + n) * 384 + kp] = __float2half_rn(u[p]);
}

__global__ void prep_a2(const float* __restrict__ src, __half* __restrict__ dst,
                        int Cpairs, size_t totalPairs)
{
    size_t i = (size_t)blockIdx.x * blockDim.x + threadIdx.x;
    if (i >= totalPairs) return;
    const int cp2 = (int)(i % (size_t)Cpairs);
    const size_t row = i / (size_t)Cpairs;
    const int c = cp2 * 2;
    const int pos = (c & ~63) | bankperm64(c & 63, (int)(row & 3));
    const float2 v = *(const float2*)(src + row * (size_t)(Cpairs * 2) + c);
    *(half2*)(dst + row * (size_t)(Cpairs * 2) + pos) = __floats2half2_rn(v.x, v.y);
}

// ---------------------------------------------------------------------------
// Host
// ---------------------------------------------------------------------------
typedef CUresult (*EncFn)(CUtensorMap*, CUtensorMapDataType, cuuint32_t, void*,
                          const cuuint64_t*, const cuuint64_t*, const cuuint32_t*,
                          const cuuint32_t*, CUtensorMapInterleave, CUtensorMapSwizzle,
                          CUtensorMapL2promotion, CUtensorMapFloatOOBfill);
static EncFn get_enc() {
    static EncFn f = nullptr;
    if (!f) {
        void* h = dlopen("libcuda.so.1", RTLD_NOW | RTLD_GLOBAL);
        if (!h) h = dlopen("libcuda.so", RTLD_NOW | RTLD_GLOBAL);
        if (h) f = (EncFn)dlsym(h, "cuTensorMapEncodeTiled");
    }
    return f;
}
static void enc5(CUtensorMap* tm, void* base, int C, int D2, int Z,
                 int box0, int box2) {
    cuuint64_t dims[5] = {(cuuint64_t)C, 32, (cuuint64_t)D2, BATCH, (cuuint64_t)Z};
    cuuint64_t strides[4] = {(cuuint64_t)C * 2, (cuuint64_t)32 * C * 2,
                             (cuuint64_t)D2 * 32 * C * 2,
                             (cuuint64_t)BATCH * D2 * 32 * C * 2};
    cuuint32_t box[5] = {(cuuint32_t)box0, 32, (cuuint32_t)box2, 1, 1};
    cuuint32_t es[5] = {1, 1, 1, 1, 1};
    get_enc()(tm, CU_TENSOR_MAP_DATA_TYPE_FLOAT16, 5, base, dims, strides, box, es,
              CU_TENSOR_MAP_INTERLEAVE_NONE, CU_TENSOR_MAP_SWIZZLE_NONE,
              CU_TENSOR_MAP_L2_PROMOTION_L2_128B, CU_TENSOR_MAP_FLOAT_OOB_FILL_NONE);
}
static void enc3(CUtensorMap* tm, void* base, int K, int Z, int box1) {
    cuuint64_t dims[3] = {(cuuint64_t)K, GATES, (cuuint64_t)Z};
    cuuint64_t strides[2] = {(cuuint64_t)K * 2, (cuuint64_t)GATES * K * 2};
    cuuint32_t box[3] = {64, (cuuint32_t)box1, 1};
    cuuint32_t es[3] = {1, 1, 1};
    get_enc()(tm, CU_TENSOR_MAP_DATA_TYPE_FLOAT16, 3, base, dims, strides, box, es,
              CU_TENSOR_MAP_INTERLEAVE_NONE, CU_TENSOR_MAP_SWIZZLE_NONE,
              CU_TENSOR_MAP_L2_PROMOTION_L2_128B, CU_TENSOR_MAP_FLOAT_OOB_FILL_NONE);
}

extern "C" void kernel_launch(void* const* d_in, const int* in_sizes, int n_in,
                              void* d_out, int out_size)
{
    const float* x  = (const float*)d_in[0];
    const float* hs = (const float*)d_in[1];
    const float* cs = (const float*)d_in[2];
    const float* Wx = (const float*)d_in[3];
    const float* Wh = (const float*)d_in[4];
    const float* bb = (const float*)d_in[5];

    float* out    = (float*)d_out;
    float* h_last = out;
    float* hs_out = out + PLANE;
    float* cs_out = out + 4 * PLANE;

    __half *WxT, *xP, *V, *UW;
    float *hbuf, *cbuf;
    cudaGetSymbolAddress((void**)&WxT,  g_WxT);
    cudaGetSymbolAddress((void**)&xP,   g_xP);
    cudaGetSymbolAddress((void**)&V,    g_V);
    cudaGetSymbolAddress((void**)&UW,   g_UW);
    cudaGetSymbolAddress((void**)&hbuf, g_hbuf);
    cudaGetSymbolAddress((void**)&cbuf, g_cbuf);

    cudaFuncSetAttribute(conv_x,  cudaFuncAttributeMaxDynamicSharedMemorySize, X_SMEM);
    cudaFuncSetAttribute(conv_wg, cudaFuncAttributeMaxDynamicSharedMemorySize, WG_SMEM);

    CUtensorMap tm_x, tm_wx, tm_v, tm_u;
    enc5(&tm_x, xP, CIN_X, 32, 1, 64, 8);       // x activations (spatial)
    enc3(&tm_wx, WxT, KX, 3, 32);               // x weights
    enc5(&tm_v, V, HID, 16, 12, 64, 4);         // V planes (row-pair space)
    enc3(&tm_u, UW, 384, 12, 8);                // Winograd weights

    // preps
    {
        int tw = 3 * KX * GATES;
        prep_w<<<(tw + 255) / 256, 256>>>(Wx, WxT, KX, tw);
        prep_wg<<<(3 * 512 * 3 * 128 + 255) / 256, 256>>>(Wh);
        size_t px = (size_t)MPOS * (CIN_X / 2);
        prep_a2<<<(unsigned)((px + 255) / 256), 256>>>(x, xP, CIN_X / 2, px);
    }

    // Gx = conv(x, Wx[l]) + b[l]   (all layers, one launch)
    conv_x<<<dim3(MPOS / 256, 4, 3), XN_TH, X_SMEM>>>(tm_x, tm_wx, bb);

    const dim3 wgrid(256, 16, 3);
    const size_t pF = PLANE * 4;
    const int vblocks = ((3 << 21) + 255) / 256;

    // r0: V from hs; c from cs -> hbuf0/cbuf0
    vtrans<<<vblocks, 256>>>((const char*)hs, pF);
    conv_wg<<<wgrid, WG_NTH, WG_SMEM>>>(
        tm_v, tm_u, (const char*)cs, pF,
        (char*)hbuf, pF, (char*)cbuf, pF, nullptr);

    // r1: V from hbuf0 -> hbuf1/cbuf1
    vtrans<<<vblocks, 256>>>((const char*)hbuf, pF);
    conv_wg<<<wgrid, WG_NTH, WG_SMEM>>>(
        tm_v, tm_u, (const char*)cbuf, pF,
        (char*)(hbuf + 3 * PLANE), pF, (char*)(cbuf + 3 * PLANE), pF, nullptr);

    // r2: V from hbuf1 -> outputs
    vtrans<<<vblocks, 256>>>((const char*)(hbuf + 3 * PLANE), pF);
    conv_wg<<<wgrid, WG_NTH, WG_SMEM>>>(
        tm_v, tm_u, (const char*)(cbuf + 3 * PLANE), pF,
        (char*)hs_out, pF, (char*)cs_out, pF, h_last);
}

// round 17
// speedup vs baseline: 1.4509x; 1.4509x over previous
#include <cuda_runtime.h>
#include <cuda.h>
#include <cuda_fp16.h>
#include <cstdint>
#include <dlfcn.h>
#include <math.h>

// ---------------------------------------------------------------------------
// Problem: B=64, H=W=32, CIN=64, HID=128, K=3, L=3, repeats=3.
// Gates=512, M=65536. Out: [h_last | hs_out(3) | cs_out(3)].
// fp16 operands, fp32 accumulate/Gx. grid.z = layer (one launch per stage).
// 16 warps = 8(M) x 2(N), warp tile 32x64 (R15 config, best known).
// ---------------------------------------------------------------------------
#define BATCH   64
#define HH      32
#define WW      32
#define CIN_X   64
#define HID     128
#define GATES   512
#define MPOS    (BATCH*HH*WW)
#define PLANE   ((size_t)MPOS*HID)
#define GXPLANE ((size_t)MPOS*GATES)
#define KX      (9*CIN_X)              // 576
#define KH      (9*HID)                // 1152

#define BM          256
#define NTH         512
#define NWARPS      16
#define STAGES      4
#define A_BYTES     32768
#define B_BYTES     16384
#define STAGE_BYTES (A_BYTES + B_BYTES)
#define SM_A(s)     ((s)*STAGE_BYTES)
#define SM_B(s)     (SM_A(s) + A_BYTES)
#define SM_BAR      (STAGES*STAGE_BYTES)
#define SMEM_TOTAL  (SM_BAR + 128)

// ---------------------------------------------------------------------------
// Device scratch
// ---------------------------------------------------------------------------
__device__ __align__(1024) __half g_WxT[3 * GATES * KX];
__device__ __align__(1024) __half g_WhT[3 * GATES * KH];
__device__ __align__(1024) __half g_xP [(size_t)MPOS * CIN_X];
__device__ __align__(1024) __half g_hsP[3 * PLANE];
__device__ __align__(1024) float  g_Gx [3 * GXPLANE];
__device__ __align__(1024) __half g_hbuf[2 * 3 * PLANE];   // [buf][layer]
__device__ __align__(1024) float  g_cbuf[2 * 3 * PLANE];

// ---------------------------------------------------------------------------
// PTX helpers
// ---------------------------------------------------------------------------
__device__ __forceinline__ uint32_t smem_u32(const void* p) {
    uint32_t a;
    asm("{ .reg .u64 t; cvta.to.shared.u64 t, %1; cvt.u32.u64 %0, t; }"
        : "=r"(a) : "l"(p));
    return a;
}
#define MBAR_INIT(addr, cnt) \
    asm volatile("mbarrier.init.shared.b64 [%0], %1;" :: "r"(addr), "r"(cnt) : "memory")
#define MBAR_ARRIVE(addr) \
    asm volatile("mbarrier.arrive.shared.b64 _, [%0];" :: "r"(addr) : "memory")
#define MBAR_EXPECT_TX(addr, bytes) \
    asm volatile("mbarrier.arrive.expect_tx.shared.b64 _, [%0], %1;" \
                 :: "r"(addr), "r"(bytes) : "memory")
#define MBAR_WAIT(addr, ph) do {                                              \
    uint32_t _m = (addr), _p = (ph), _d;                                      \
    asm volatile("{\n\t.reg .pred p;\n\t"                                     \
        "mbarrier.try_wait.parity.acquire.cta.shared::cta.b64 p, [%1], %2;\n\t" \
        "selp.b32 %0, 1, 0, p;\n\t}" : "=r"(_d) : "r"(_m), "r"(_p) : "memory");\
    if (!_d) {                                                                \
        asm volatile("{\n\t.reg .pred P1;\n\tWL_%=:\n\t"                      \
            "mbarrier.try_wait.parity.acquire.cta.shared::cta.b64 P1, [%0], %1, 0x989680;\n\t" \
            "@P1 bra.uni WD_%=;\n\tbra.uni WL_%=;\n\tWD_%=:\n\t}"             \
            :: "r"(_m), "r"(_p) : "memory");                                  \
    } } while (0)

#define TMA_LD_5D(dst, map, c0_, c1_, c2_, c3_, c4_, mbar) \
    asm volatile("cp.async.bulk.tensor.5d.shared::cta.global.tile.mbarrier::complete_tx::bytes " \
        "[%0], [%1, {%2, %3, %4, %5, %6}], [%7];" \
        :: "r"(dst), "l"(map), "r"(c0_), "r"(c1_), "r"(c2_), "r"(c3_), "r"(c4_), "r"(mbar) : "memory")
#define TMA_LD_3D(dst, map, c0_, c1_, c2_, mbar) \
    asm volatile("cp.async.bulk.tensor.3d.shared::cta.global.tile.mbarrier::complete_tx::bytes " \
        "[%0], [%1, {%2, %3, %4}], [%5];" \
        :: "r"(dst), "l"(map), "r"(c0_), "r"(c1_), "r"(c2_), "r"(mbar) : "memory")

__device__ __forceinline__ uint2 lds64(uint32_t addr) {
    uint2 r;
    asm("ld.shared.v2.b32 {%0,%1}, [%2];" : "=r"(r.x), "=r"(r.y) : "r"(addr));
    return r;
}

// m16n8k16 fp16 mma, fp32 accumulate
__device__ __forceinline__ void mma16(float* d, const uint32_t* a, const uint32_t* b) {
    asm volatile("mma.sync.aligned.m16n8k16.row.col.f32.f16.f16.f32 "
        "{%0,%1,%2,%3}, {%4,%5,%6,%7}, {%8,%9}, {%0,%1,%2,%3};"
        : "+f"(d[0]), "+f"(d[1]), "+f"(d[2]), "+f"(d[3])
        : "r"(a[0]), "r"(a[1]), "r"(a[2]), "r"(a[3]), "r"(b[0]), "r"(b[1]));
}

__device__ __forceinline__ int perm16(int k) {
    return 4 * ((k & 7) >> 1) + 2 * (k >> 3) + (k & 1);
}
__device__ __forceinline__ int bankperm64(int c, int row) {
    return ((((c >> 4) & 3) ^ (row & 3)) << 4) | perm16(c & 15);
}
__device__ __forceinline__ float sigm(float v) { return 1.f / (1.f + __expf(-v)); }

// ---------------------------------------------------------------------------
// Fused implicit-GEMM conv via fp16 mma.sync m16n8k16 (fp32 accum).
// grid = (M/BM, 4, 3): blockIdx.z = layer. 16 warps = 8(M) x 2(N), tile 32x64.
// Chunk = 64 fp16 channels. A swizzle key = global x&3 (dx-compensated).
// Each warp owns 2 sub-columns of EVERY gate -> fused epilogue thread-local.
// ---------------------------------------------------------------------------
template<int CPT, int NCHUNK, bool FUSED, bool PERM>
__global__ __launch_bounds__(NTH, 1)
void conv_tc(const __grid_constant__ CUtensorMap a_map,
             const __grid_constant__ CUtensorMap b_map,
             int a_z0, int a_zstep,
             const char* __restrict__ add_src, size_t add_stride,
             const char* __restrict__ c_in,    size_t cin_stride,
             char* __restrict__ out0,          size_t out0_stride,
             char* __restrict__ c_out,         size_t cout_stride,
             float* __restrict__ h_dup)        // only used when layer==2
{
    extern __shared__ __align__(1024) char smem[];
    const uint32_t sb = smem_u32(smem);
    const int tid  = threadIdx.x;
    const int lane = tid & 31;
    const int wid  = tid >> 5;
    const int wm   = wid & 7;            // M slice (32 rows)
    const int wn   = wid >> 3;           // N half (0/1)
    const int l    = blockIdx.z;
    const int a_z  = a_z0 + l * a_zstep;
    const int b_z  = l;

    const uint32_t FULL  = sb + SM_BAR;
    const uint32_t EMPTY = sb + SM_BAR + 32;

    if (tid == 0) {
#pragma unroll
        for (int s = 0; s < STAGES; s++) {
            MBAR_INIT(FULL + 8*s, 1);
            MBAR_INIT(EMPTY + 8*s, NWARPS);
        }
    }
    __syncthreads();

    const int c0   = blockIdx.y * 32;
    const int m0   = blockIdx.x * BM;
    const int bimg = m0 >> 10;
    const int y0   = (m0 >> 5) & 31;

    if (tid == 0) {
#pragma unroll
        for (int kc = 0; kc < STAGES; kc++) {
            const int s = kc;
            MBAR_EXPECT_TX(FULL + 8*s, (uint32_t)STAGE_BYTES);
            const int tap = kc / CPT, cc = (kc % CPT) * 64;
            const int dy = tap / 3 - 1, dx = tap % 3 - 1;
            TMA_LD_5D(sb + SM_A(s), &a_map, cc, dx, y0 + dy, bimg, a_z, FULL + 8*s);
            const int k0 = kc * 64;
#pragma unroll
            for (int g = 0; g < 4; g++)
                TMA_LD_3D(sb + SM_B(s) + g * 4096, &b_map, k0, g * 128 + c0, b_z,
                          FULL + 8*s);
        }
    }

    float acc[2][8][4];   // [mi][g*2+s2][frag]
#pragma unroll
    for (int mi = 0; mi < 2; mi++)
#pragma unroll
        for (int ni = 0; ni < 8; ni++)
#pragma unroll
            for (int j = 0; j < 4; j++) acc[mi][ni][j] = 0.f;

    const int q4 = lane >> 2;
    const int t4 = lane & 3;
    const uint32_t xorB = (uint32_t)(q4 & 3) << 5;

    for (int kc = 0; kc < NCHUNK; kc++) {
        const int s = kc & 3;
        const uint32_t u = (kc >> 2) & 1;
        MBAR_WAIT(FULL + 8*s, u);

        const int tap = kc / CPT;
        const int dxA = tap % 3 - 1;
        const uint32_t xorA = (uint32_t)((q4 + dxA) & 3) << 5;

        const uint32_t aW = sb + SM_A(s) + (uint32_t)wm * 4096 + ((uint32_t)q4 << 7);
        const uint32_t bW = sb + SM_B(s) + (uint32_t)wn * 2048 + ((uint32_t)q4 << 7);

#pragma unroll
        for (int ks = 0; ks < 4; ks++) {
            const uint32_t koffA = (((uint32_t)(ks * 32)) ^ xorA) + (uint32_t)(t4 * 8);
            const uint32_t koffB = (((uint32_t)(ks * 32)) ^ xorB) + (uint32_t)(t4 * 8);

            uint2 aLo[2], aHi[2];
#pragma unroll
            for (int mi = 0; mi < 2; mi++) {
                aLo[mi] = lds64(aW + (uint32_t)mi * 2048 + koffA);
                aHi[mi] = lds64(aW + (uint32_t)mi * 2048 + 1024 + koffA);
            }
            uint2 bfr[8];
#pragma unroll
            for (int g = 0; g < 4; g++)
#pragma unroll
                for (int s2 = 0; s2 < 2; s2++)
                    bfr[g*2+s2] = lds64(bW + (uint32_t)g * 4096
                                           + (uint32_t)s2 * 1024 + koffB);
#pragma unroll
            for (int mi = 0; mi < 2; mi++) {
                const uint32_t af[4] = {aLo[mi].x, aHi[mi].x, aLo[mi].y, aHi[mi].y};
#pragma unroll
                for (int ni = 0; ni < 8; ni++)
                    mma16(acc[mi][ni], af, &bfr[ni].x);
            }
        }

        if (lane == 0) MBAR_ARRIVE(EMPTY + 8*s);

        if (tid == 0 && kc + STAGES < NCHUNK) {
            MBAR_WAIT(EMPTY + 8*s, u);
            MBAR_EXPECT_TX(FULL + 8*s, (uint32_t)STAGE_BYTES);
            const int kn = kc + STAGES;
            const int tapn = kn / CPT, cc = (kn % CPT) * 64;
            const int dy = tapn / 3 - 1, dx = tapn % 3 - 1;
            TMA_LD_5D(sb + SM_A(s), &a_map, cc, dx, y0 + dy, bimg, a_z, FULL + 8*s);
            const int k0 = kn * 64;
#pragma unroll
            for (int g = 0; g < 4; g++)
                TMA_LD_3D(sb + SM_B(s) + g * 4096, &b_map, k0, g * 128 + c0, b_z,
                          FULL + 8*s);
        }
    }

    // ------------------------- epilogue -------------------------
    if (FUSED) {
        const float* gxl = (const float*)(add_src + (size_t)l * add_stride);
        const float* cil = (const float*)(c_in + (size_t)l * cin_stride);
        float*  coutl = (float*)(c_out + (size_t)l * cout_stride);
        __half* o16   = (__half*)(out0 + (size_t)l * out0_stride);
        float*  o32   = (float*)(out0 + (size_t)l * out0_stride);
        float*  hd    = (h_dup && l == 2) ? h_dup : nullptr;
#pragma unroll
        for (int mi = 0; mi < 2; mi++)
#pragma unroll
            for (int h = 0; h < 2; h++) {
                const int m = m0 + wm * 32 + mi * 16 + q4 + 8 * h;
                const int j = 2 * h;
#pragma unroll
                for (int s2 = 0; s2 < 2; s2++) {
                    const int nqe = wn * 2 + s2;
                    const int ch = c0 + nqe * 8 + t4 * 2;
                    const float* gxp = gxl + (size_t)m * GATES + ch;
                    const float2 gi = *(const float2*)(gxp);
                    const float2 gf = *(const float2*)(gxp + 128);
                    const float2 gg = *(const float2*)(gxp + 256);
                    const float2 go = *(const float2*)(gxp + 384);
                    const float2 cv = *(const float2*)(cil + (size_t)m * HID + ch);

                    const float i0 = acc[mi][s2][j]      + gi.x;
                    const float i1 = acc[mi][s2][j+1]    + gi.y;
                    const float f0 = acc[mi][2+s2][j]    + gf.x;
                    const float f1 = acc[mi][2+s2][j+1]  + gf.y;
                    const float g0 = acc[mi][4+s2][j]    + gg.x;
                    const float g1 = acc[mi][4+s2][j+1]  + gg.y;
                    const float o0 = acc[mi][6+s2][j]    + go.x;
                    const float o1 = acc[mi][6+s2][j+1]  + go.y;

                    float2 cn, hn;
                    cn.x = sigm(f0) * cv.x + sigm(i0) * tanhf(g0);
                    cn.y = sigm(f1) * cv.y + sigm(i1) * tanhf(g1);
                    hn.x = sigm(o0) * tanhf(cn.x);
                    hn.y = sigm(o1) * tanhf(cn.y);

                    const size_t ob = (size_t)m * HID + ch;
                    *(float2*)(coutl + ob) = cn;
                    if (PERM) {
                        const int c64 = ch & 63;
                        const int G   = (c64 >> 4) ^ (m & 3);
                        const int a2  = (c64 & 15) >> 1;
                        const int p   = 4 * (a2 & 3) + 2 * (a2 >> 2);
                        const int pos = (ch & ~63) + (G << 4) + p;
                        *(half2*)(o16 + (size_t)m * HID + pos) =
                            __floats2half2_rn(hn.x, hn.y);
                    } else {
                        *(float2*)(o32 + ob) = hn;
                        if (hd) *(float2*)(hd + ob) = hn;
                    }
                }
            }
    } else {
        const float* bl = (const float*)(add_src + (size_t)l * add_stride);
        float* gxo = (float*)(out0 + (size_t)l * out0_stride);
#pragma unroll
        for (int mi = 0; mi < 2; mi++)
#pragma unroll
            for (int h = 0; h < 2; h++) {
                const int m = m0 + wm * 32 + mi * 16 + q4 + 8 * h;
                const int j = 2 * h;
#pragma unroll
                for (int g = 0; g < 4; g++)
#pragma unroll
                    for (int s2 = 0; s2 < 2; s2++) {
                        const int gcol = g * 128 + c0 + (wn * 2 + s2) * 8 + t4 * 2;
                        const float2 bv = *(const float2*)(bl + gcol);
                        float2 v;
                        v.x = acc[mi][g*2+s2][j]   + bv.x;
                        v.y = acc[mi][g*2+s2][j+1] + bv.y;
                        *(float2*)(gxo + (size_t)m * GATES + gcol) = v;
                    }
            }
    }
}

// ---------------------------------------------------------------------------
// Combined weight prep: both Wx and Wh in ONE launch (index-range dispatch).
// fp32 -> fp16 with bank-swizzled 64-channel K layout.
// ---------------------------------------------------------------------------
__global__ void prep_w2(const float* __restrict__ Wx, const float* __restrict__ Wh,
                        __half* __restrict__ dWx, __half* __restrict__ dWh,
                        int twx, int total)
{
    int i = blockIdx.x * blockDim.x + threadIdx.x;
    if (i >= total) return;
    const float* src; __half* dst; int K, j;
    if (i < twx) { src = Wx; dst = dWx; K = KX; j = i; }
    else         { src = Wh; dst = dWh; K = KH; j = i - twx; }
    int n = j % GATES;
    int k = (j / GATES) % K;
    int l = j / (GATES * K);
    int kp = (k & ~63) | bankperm64(k & 63, n);
    dst[((size_t)l * GATES + n) * K + kp] = __float2half_rn(src[j]);
}

// ---------------------------------------------------------------------------
// Combined activation prep: x and hs in ONE launch, QUAD-vectorized.
// For c % 4 == 0: perm position of (c,c+1) = pos, of (c+2,c+3) = pos+4
// (verified: perm16(k+2) = perm16(k)+4 for even k; bank group unchanged).
// One float4 read -> two half2 writes.
// ---------------------------------------------------------------------------
__global__ void prep_aq(const float* __restrict__ x, const float* __restrict__ hs,
                        __half* __restrict__ xP, __half* __restrict__ hsP,
                        size_t qx, size_t total)
{
    size_t i = (size_t)blockIdx.x * blockDim.x + threadIdx.x;
    if (i >= total) return;
    const float* src; __half* dst; int C; size_t j;
    if (i < qx) { src = x;  dst = xP;  C = CIN_X; j = i; }
    else        { src = hs; dst = hsP; C = HID;   j = i - qx; }
    const int Cq = C >> 2;
    const int cq = (int)(j % (size_t)Cq);
    const size_t row = j / (size_t)Cq;
    const int c = cq * 4;
    const int key = (int)(row & 3);
    const int pos = (c & ~63) | bankperm64(c & 63, key);
    const float4 v = *(const float4*)(src + row * (size_t)C + c);
    __half* d = dst + row * (size_t)C;
    *(half2*)(d + pos)     = __floats2half2_rn(v.x, v.y);
    *(half2*)(d + pos + 4) = __floats2half2_rn(v.z, v.w);
}

// ---------------------------------------------------------------------------
// Host: tensormap encoding via dlopen
// ---------------------------------------------------------------------------
typedef CUresult (*EncFn)(CUtensorMap*, CUtensorMapDataType, cuuint32_t, void*,
                          const cuuint64_t*, const cuuint64_t*, const cuuint32_t*,
                          const cuuint32_t*, CUtensorMapInterleave, CUtensorMapSwizzle,
                          CUtensorMapL2promotion, CUtensorMapFloatOOBfill);
static EncFn get_enc() {
    static EncFn f = nullptr;
    if (!f) {
        void* h = dlopen("libcuda.so.1", RTLD_NOW | RTLD_GLOBAL);
        if (!h) h = dlopen("libcuda.so", RTLD_NOW | RTLD_GLOBAL);
        if (h) f = (EncFn)dlsym(h, "cuTensorMapEncodeTiled");
    }
    return f;
}

static void enc_act5(CUtensorMap* tm, void* base, int C, int Z) {
    cuuint64_t dims[5]    = {(cuuint64_t)C, WW, HH, BATCH, (cuuint64_t)Z};
    cuuint64_t strides[4] = {(cuuint64_t)C * 2, (cuuint64_t)WW * C * 2,
                             (cuuint64_t)HH * WW * C * 2,
                             (cuuint64_t)BATCH * HH * WW * C * 2};
    cuuint32_t box[5] = {64, WW, 8, 1, 1};
    cuuint32_t es[5]  = {1, 1, 1, 1, 1};
    get_enc()(tm, CU_TENSOR_MAP_DATA_TYPE_FLOAT16, 5, base, dims, strides, box, es,
              CU_TENSOR_MAP_INTERLEAVE_NONE, CU_TENSOR_MAP_SWIZZLE_NONE,
              CU_TENSOR_MAP_L2_PROMOTION_L2_128B, CU_TENSOR_MAP_FLOAT_OOB_FILL_NONE);
}
static void enc_w3(CUtensorMap* tm, void* base, int K) {
    cuuint64_t dims[3]    = {(cuuint64_t)K, GATES, 3};
    cuuint64_t strides[2] = {(cuuint64_t)K * 2, (cuuint64_t)GATES * K * 2};
    cuuint32_t box[3] = {64, 32, 1};
    cuuint32_t es[3]  = {1, 1, 1};
    get_enc()(tm, CU_TENSOR_MAP_DATA_TYPE_FLOAT16, 3, base, dims, strides, box, es,
              CU_TENSOR_MAP_INTERLEAVE_NONE, CU_TENSOR_MAP_SWIZZLE_NONE,
              CU_TENSOR_MAP_L2_PROMOTION_L2_128B, CU_TENSOR_MAP_FLOAT_OOB_FILL_NONE);
}

extern "C" void kernel_launch(void* const* d_in, const int* in_sizes, int n_in,
                              void* d_out, int out_size)
{
    const float* x  = (const float*)d_in[0];
    const float* hs = (const float*)d_in[1];
    const float* cs = (const float*)d_in[2];
    const float* Wx = (const float*)d_in[3];
    const float* Wh = (const float*)d_in[4];
    const float* bb = (const float*)d_in[5];

    float* out    = (float*)d_out;
    float* h_last = out;
    float* hs_out = out + PLANE;
    float* cs_out = out + 4 * PLANE;

    __half *WxT, *WhT, *xP, *hsP, *hbuf;
    float  *Gx, *cbuf;
    cudaGetSymbolAddress((void**)&WxT,  g_WxT);
    cudaGetSymbolAddress((void**)&WhT,  g_WhT);
    cudaGetSymbolAddress((void**)&xP,   g_xP);
    cudaGetSymbolAddress((void**)&hsP,  g_hsP);
    cudaGetSymbolAddress((void**)&Gx,   g_Gx);
    cudaGetSymbolAddress((void**)&hbuf, g_hbuf);
    cudaGetSymbolAddress((void**)&cbuf, g_cbuf);

    cudaFuncSetAttribute(conv_tc<1, 9, false, false>,
                         cudaFuncAttributeMaxDynamicSharedMemorySize, SMEM_TOTAL);
    cudaFuncSetAttribute(conv_tc<2, 18, true, true>,
                         cudaFuncAttributeMaxDynamicSharedMemorySize, SMEM_TOTAL);
    cudaFuncSetAttribute(conv_tc<2, 18, true, false>,
                         cudaFuncAttributeMaxDynamicSharedMemorySize, SMEM_TOTAL);

    CUtensorMap tm_x, tm_hs, tm_hb, tm_wx, tm_wh;
    enc_act5(&tm_x,  xP,   CIN_X, 1);
    enc_act5(&tm_hs, hsP,  HID,   3);
    enc_act5(&tm_hb, hbuf, HID,   6);   // [buf0 l0..l2 | buf1 l0..l2]
    enc_w3(&tm_wx, WxT, KX);
    enc_w3(&tm_wh, WhT, KH);

    // pre-passes (2 launches)
    {
        const int twx = 3 * KX * GATES, tw = twx + 3 * KH * GATES;
        prep_w2<<<(tw + 255) / 256, 256>>>(Wx, Wh, WxT, WhT, twx, tw);
        const size_t qx = (size_t)MPOS * (CIN_X / 4);
        const size_t qt = qx + 3 * PLANE / 4;
        prep_aq<<<(unsigned)((qt + 255) / 256), 256>>>(x, hs, xP, hsP, qx, qt);
    }

    const dim3 grid(MPOS / BM, 4, 3);        // all 3 layers per launch
    const size_t gxS = GXPLANE * 4;          // Gx per-layer bytes (fp32)
    const size_t pF  = PLANE * 4;            // fp32 plane bytes
    const size_t pH  = PLANE * 2;            // fp16 plane bytes

    // Gx[l] = conv(x, Wx[l]) + b[l]   (repeat-invariant)
    conv_tc<1, 9, false, false><<<grid, NTH, SMEM_TOTAL>>>(
        tm_x, tm_wx, 0, 0,
        (const char*)bb, GATES * 4,
        nullptr, 0,
        (char*)Gx, gxS,
        nullptr, 0, nullptr);

    // r0: hsP[l]/cs[l] -> hbuf[0][l] (fp16 perm) / cbuf[0][l]
    conv_tc<2, 18, true, true><<<grid, NTH, SMEM_TOTAL>>>(
        tm_hs, tm_wh, 0, 1,
        (const char*)Gx, gxS,
        (const char*)cs, pF,
        (char*)hbuf, pH,
        (char*)cbuf, pF, nullptr);

    // r1: hbuf[0][l]/cbuf[0][l] -> hbuf[1][l] / cbuf[1][l]
    conv_tc<2, 18, true, true><<<grid, NTH, SMEM_TOTAL>>>(
        tm_hb, tm_wh, 0, 1,
        (const char*)Gx, gxS,
        (const char*)cbuf, pF,
        (char*)(hbuf + 3 * PLANE), pH,
        (char*)(cbuf + 3 * PLANE), pF, nullptr);

    // r2: hbuf[1][l]/cbuf[1][l] -> output slices (fp32, natural order)
    conv_tc<2, 18, true, false><<<grid, NTH, SMEM_TOTAL>>>(
        tm_hb, tm_wh, 3, 1,
        (const char*)Gx, gxS,
        (const char*)(cbuf + 3 * PLANE), pF,
        (char*)hs_out, pF,
        (char*)cs_out, pF, h_last);
}